// round 7
// baseline (speedup 1.0000x reference)
#include <cuda_runtime.h>
#include <cuda_bf16.h>
#include <cstdint>

// Problem constants (fixed by the dataset)
#define B_  4
#define T_  2048
#define NH_ 8
#define N_  64
#define D_  128
#define C_  128          // chunk length
#define NC_ 16           // T_/C_
#define OUT_ELEMS (B_*T_*NH_*D_)   // 8,388,608
#define ST_ELEMS  (B_*NH_*N_*D_)   // 262,144

// Scratch:
//  g_dS        : per-chunk delta-state, layout [bh*16+k][d][n] fp32
//  g_sph/g_spl : prefix state (state + sum_{j<k} dS_j), bf16 hi/lo planes, [blk][d][n]
__device__ float         g_dS [(size_t)512*8192];
__device__ __nv_bfloat16 g_sph[(size_t)512*8192];
__device__ __nv_bfloat16 g_spl[(size_t)512*8192];

// ---------------------------------------------------------------------------
// helpers
// ---------------------------------------------------------------------------
__device__ __forceinline__ uint32_t smem_u32(const void* p) {
    uint32_t a;
    asm("{ .reg .u64 t; cvta.to.shared.u64 t, %1; cvt.u32.u64 %0, t; }"
        : "=r"(a) : "l"(p));
    return a;
}
__device__ __forceinline__ void ldmx4(uint32_t* r, uint32_t a) {
    asm volatile("ldmatrix.sync.aligned.m8n8.x4.shared.b16 {%0,%1,%2,%3}, [%4];"
                 : "=r"(r[0]), "=r"(r[1]), "=r"(r[2]), "=r"(r[3]) : "r"(a));
}
__device__ __forceinline__ void ldmx4t(uint32_t* r, uint32_t a) {
    asm volatile("ldmatrix.sync.aligned.m8n8.x4.trans.shared.b16 {%0,%1,%2,%3}, [%4];"
                 : "=r"(r[0]), "=r"(r[1]), "=r"(r[2]), "=r"(r[3]) : "r"(a));
}
// D += A * B, m16n8k16, row.col, bf16 in / fp32 accum
__device__ __forceinline__ void mma(float* d, const uint32_t* a, const uint32_t* b) {
    asm volatile("mma.sync.aligned.m16n8k16.row.col.f32.bf16.bf16.f32 "
                 "{%0,%1,%2,%3}, {%4,%5,%6,%7}, {%8,%9}, {%0,%1,%2,%3};"
                 : "+f"(d[0]), "+f"(d[1]), "+f"(d[2]), "+f"(d[3])
                 : "r"(a[0]), "r"(a[1]), "r"(a[2]), "r"(a[3]),
                   "r"(b[0]), "r"(b[1]));
}
// fp32 pair -> packed bf16x2 hi plane + residual lo plane (a in low half).
// cvt.rn.bf16x2.f32 packs {b,a}; residuals via exact bit-mask widening.
__device__ __forceinline__ void split2(float a, float b, uint32_t& hi, uint32_t& lo) {
    uint32_t h;
    asm("cvt.rn.bf16x2.f32 %0, %1, %2;" : "=r"(h) : "f"(b), "f"(a));
    float la = a - __uint_as_float(h << 16);
    float lb = b - __uint_as_float(h & 0xffff0000u);
    uint32_t l;
    asm("cvt.rn.bf16x2.f32 %0, %1, %2;" : "=r"(l) : "f"(lb), "f"(la));
    hi = h; lo = l;
}

// padded row stride (elements): 4-bank row offset -> conflict-free ldmatrix
#define S64  72     // rows of 64 bf16

// ============================================================================
// Kernel A (d-split): dS^T[dh*64+dl][n] = sum_c V[c][dh*64+dl] * Q[c][n]
//   smem: V natural [c=128][d-half=64] hi/lo ; Q natural [c=128][n=64] hi/lo
//   A = V^T via ldmatrix.trans ; B = Q^T via ldmatrix.trans (plane-mixed x4)
// grid = 1024 (cidx*2+dh), 256 threads, 3 CTAs/SM
// warps: wd = w&3 (16-row d tile), nh = w>>2 (32-col n half); j = 4 n8 tiles
// ============================================================================
#define KA_SMEM ((size_t)(4*128*S64)*2)   // 73,728 B

__global__ __launch_bounds__(256, 3) void kA(const float* __restrict__ Q,
                                             const float* __restrict__ V) {
    extern __shared__ __nv_bfloat16 sm[];
    __nv_bfloat16* Vh = sm;                  // [128][S64]
    __nv_bfloat16* Vl = Vh + 128 * S64;
    __nv_bfloat16* Qh = Vl + 128 * S64;      // [128][S64]
    __nv_bfloat16* Ql = Qh + 128 * S64;

    const int tid = threadIdx.x, w = tid >> 5, L = tid & 31;
    const int cidx = blockIdx.x >> 1, dh = blockIdx.x & 1;
    const int k = cidx & 15, bh = cidx >> 4;
    const int b = bh >> 3, h = bh & 7;

    const float* Qb = Q + ((size_t)(b * T_ + k * C_) * NH_ + h) * N_;
    const float* Vb = V + (size_t)(b * T_ + k * C_) * D_ + dh * 64;

    // Q natural [c][n]: coalesced float4 loads
#pragma unroll
    for (int it = 0; it < 8; it++) {
        int idx = tid + it * 256;                 // 2048 float4
        int n4 = idx & 15, c = idx >> 4;
        float4 q = *(const float4*)(Qb + (size_t)c * (NH_ * N_) + n4 * 4);
        uint32_t h0, l0, h1, l1;
        split2(q.x, q.y, h0, l0);
        split2(q.z, q.w, h1, l1);
        *(uint2*)(Qh + c * S64 + n4 * 4) = make_uint2(h0, h1);
        *(uint2*)(Ql + c * S64 + n4 * 4) = make_uint2(l0, l1);
    }
    // V natural [c][d-half]
#pragma unroll
    for (int it = 0; it < 8; it++) {
        int idx = tid + it * 256;                 // 2048 float4
        int d4 = idx & 15, c = idx >> 4;
        float4 v = *(const float4*)(Vb + (size_t)c * D_ + d4 * 4);
        uint32_t h0, l0, h1, l1;
        split2(v.x, v.y, h0, l0);
        split2(v.z, v.w, h1, l1);
        *(uint2*)(Vh + c * S64 + d4 * 4) = make_uint2(h0, h1);
        *(uint2*)(Vl + c * S64 + d4 * 4) = make_uint2(l0, l1);
    }
    __syncthreads();

    const int wd = w & 3, nh = w >> 2;
    // A (V^T, m = d-local rows 16wd..16wd+15) trans x4
    const uint32_t aA = smem_u32(
        Vh + ((L & 7) + ((L >> 4) << 3)) * S64 + 16 * wd + (((L >> 3) & 1) << 3));
    const uint32_t VPL = 128 * S64 * 2;          // hi->lo plane (bytes)
    // B (Q^T) trans x4 plane-mixed: lanes 0-15 hi rows c0-15, lanes 16-31 lo
    const uint32_t aB = smem_u32((L < 16 ? Qh : Ql) + (L & 15) * S64) + nh * 64;

    float acc[4][4];
#pragma unroll
    for (int j = 0; j < 4; j++)
#pragma unroll
        for (int q = 0; q < 4; q++) acc[j][q] = 0.f;

#pragma unroll
    for (int kk = 0; kk < 8; kk++) {
        uint32_t ah[4], al[4];
        ldmx4t(ah, aA + kk * (16 * S64 * 2));
        ldmx4t(al, aA + VPL + kk * (16 * S64 * 2));
#pragma unroll
        for (int j = 0; j < 4; j++) {
            uint32_t br[4];   // {bh0, bh1, bl0, bl1}
            ldmx4t(br, aB + kk * (16 * S64 * 2) + j * 16);
            mma(acc[j], ah, br);
            mma(acc[j], ah, br + 2);
            mma(acc[j], al, br);
        }
    }

    const int r0 = dh * 64 + 16 * wd + (L >> 2);
    const int cc = nh * 32 + (L & 3) * 2;
    float* op = g_dS + (size_t)cidx * 8192;
#pragma unroll
    for (int j = 0; j < 4; j++) {
        *(float2*)(op + (size_t)r0 * 64 + 8 * j + cc)       = make_float2(acc[j][0], acc[j][1]);
        *(float2*)(op + (size_t)(r0 + 8) * 64 + 8 * j + cc) = make_float2(acc[j][2], acc[j][3]);
    }
}

// ============================================================================
// Kernel B: exclusive prefix over the 16 chunks -> bf16 hi/lo planes + new_state
// ============================================================================
__global__ void kB(const float* __restrict__ state, float* __restrict__ out_state) {
    int gid = blockIdx.x * 256 + threadIdx.x;       // < 262144
    int bh = gid >> 13, dn = gid & 8191;
    int d = dn >> 6, n = dn & 63;
    const size_t base = (size_t)bh * NC_ * 8192 + dn;
    float run = state[((size_t)bh * 64 + n) * 128 + d];
#pragma unroll
    for (int k = 0; k < NC_; k++) {
        float v = g_dS[base + (size_t)k * 8192];
        uint32_t hi, lo;
        split2(run, 0.f, hi, lo);
        g_sph[base + (size_t)k * 8192] = __ushort_as_bfloat16((unsigned short)(hi & 0xffff));
        g_spl[base + (size_t)k * 8192] = __ushort_as_bfloat16((unsigned short)(lo & 0xffff));
        run += v;
    }
    if (out_state) out_state[((size_t)bh * 64 + n) * 128 + d] = run;
}

// ============================================================================
// Kernel C (d-split): per (chunk, d-half):
//   scores = tril(Q Q^T, -1)   (full u range, register accum, masked -> A frags)
//   out[:, dh] = Q @ Spref[:, dh] + scores @ V[:, dh]
//   smem: Q natural [t][n] hi/lo ; Spref^T [d-local 64][n] hi/lo ;
//         V natural [u][d-local 64] hi/lo
// grid = 1024 (cidx*2+dh), 256 threads, 2 CTAs/SM
// ============================================================================
#define KC_SMEM ((size_t)(2*128*S64 + 2*64*S64 + 2*128*S64)*2)   // 92,160 B

__global__ __launch_bounds__(256, 2) void kC(const float* __restrict__ Q,
                                             const float* __restrict__ V,
                                             float* __restrict__ out) {
    extern __shared__ __nv_bfloat16 sm[];
    __nv_bfloat16* Qh = sm;                 // [128][S64]  Q[t][n]
    __nv_bfloat16* Ql = Qh + 128 * S64;
    __nv_bfloat16* Sh = Ql + 128 * S64;     // [64][S64]   Spref^T[d-local][n]
    __nv_bfloat16* Sl = Sh + 64 * S64;
    __nv_bfloat16* Vh = Sl + 64 * S64;      // [128][S64]  V[u][d-local]
    __nv_bfloat16* Vl = Vh + 128 * S64;

    const int tid = threadIdx.x, w = tid >> 5, L = tid & 31;
    const int cidx = blockIdx.x >> 1, dh = blockIdx.x & 1;
    const int k = cidx & 15, bh = cidx >> 4;
    const int b = bh >> 3, h = bh & 7;

    const float* Qb = Q + ((size_t)(b * T_ + k * C_) * NH_ + h) * N_;
    const float* Vb = V + (size_t)(b * T_ + k * C_) * D_ + dh * 64;

    // Q natural [t][n]
#pragma unroll
    for (int it = 0; it < 8; it++) {
        int idx = tid + it * 256;                 // 2048 float4
        int n4 = idx & 15, t = idx >> 4;
        float4 q = *(const float4*)(Qb + (size_t)t * (NH_ * N_) + n4 * 4);
        uint32_t h0, l0, h1, l1;
        split2(q.x, q.y, h0, l0);
        split2(q.z, q.w, h1, l1);
        *(uint2*)(Qh + t * S64 + n4 * 4) = make_uint2(h0, h1);
        *(uint2*)(Ql + t * S64 + n4 * 4) = make_uint2(l0, l1);
    }
    // Spref planes: straight 16B copies of [d][n] bf16 (rows dh*64 .. dh*64+63)
#pragma unroll
    for (int it = 0; it < 2; it++) {
        int idx = tid + it * 256;                 // 512 uint4 per plane
        int ch = idx & 7, dl = idx >> 3;
        size_t sbase = (size_t)cidx * 8192 + (size_t)(dh * 64 + dl) * 64 + ch * 8;
        *(uint4*)(Sh + dl * S64 + ch * 8) = *(const uint4*)(g_sph + sbase);
        *(uint4*)(Sl + dl * S64 + ch * 8) = *(const uint4*)(g_spl + sbase);
    }
    // V natural [u][d-local]
#pragma unroll
    for (int it = 0; it < 8; it++) {
        int idx = tid + it * 256;                 // 2048 float4
        int d4 = idx & 15, u = idx >> 4;
        float4 v = *(const float4*)(Vb + (size_t)u * D_ + d4 * 4);
        uint32_t h0, l0, h1, l1;
        split2(v.x, v.y, h0, l0);
        split2(v.z, v.w, h1, l1);
        *(uint2*)(Vh + u * S64 + d4 * 4) = make_uint2(h0, h1);
        *(uint2*)(Vl + u * S64 + d4 * 4) = make_uint2(l0, l1);
    }
    __syncthreads();

    const int Lm = L & 15;
    // A (Q rows 16w..16w+15) non-trans x4 (per plane)
    const uint32_t aQA = smem_u32(Qh + (16 * w + Lm) * S64 + ((L >> 4) << 3));
    const uint32_t QOFF = 128 * S64 * 2;     // hi -> lo plane (bytes)
    // B non-trans plane-mixed x4 (rows j*8+(L&7), col-half (L>>3)&1)
    const uint32_t aQB = smem_u32((L < 16 ? Qh : Ql) + (L & 7) * S64 + (((L >> 3) & 1) << 3));
    const uint32_t aSB = smem_u32((L < 16 ? Sh : Sl) + (L & 7) * S64 + (((L >> 3) & 1) << 3));
    // B (V^T) trans plane-mixed x4: lanes 0-15 hi rows u0-15, lanes 16-31 lo
    const uint32_t aVB = smem_u32((L < 16 ? Vh : Vl) + (L & 15) * S64);

    const int r0 = 16 * w + (L >> 2);

    // ---- Phase 1: scores = tril(Q Q^T, -1), two j-halves to cap registers ----
    uint32_t PAh[8][4], PAl[8][4];
#pragma unroll
    for (int jb = 0; jb < 2; jb++) {
        float sc[8][4];
#pragma unroll
        for (int j = 0; j < 8; j++)
#pragma unroll
            for (int q = 0; q < 4; q++) sc[j][q] = 0.f;

#pragma unroll
        for (int kk = 0; kk < 4; kk++) {
            uint32_t ah[4], al[4];
            ldmx4(ah, aQA + kk * 32);
            ldmx4(al, aQA + QOFF + kk * 32);
#pragma unroll
            for (int j = 0; j < 8; j++) {
                uint32_t br[4];
                ldmx4(br, aQB + (jb * 8 + j) * (8 * S64 * 2) + kk * 32);
                mma(sc[j], ah, br);
                mma(sc[j], ah, br + 2);
                mma(sc[j], al, br);
            }
        }
        // mask (strict tril) + convert to phase-3 A-fragments
#pragma unroll
        for (int j = 0; j < 8; j++) {
            int jj = jb * 8 + j;
            int u0 = 8 * jj + (L & 3) * 2;
            float x0 = (u0     < r0)     ? sc[j][0] : 0.f;
            float x1 = (u0 + 1 < r0)     ? sc[j][1] : 0.f;
            float x2 = (u0     < r0 + 8) ? sc[j][2] : 0.f;
            float x3 = (u0 + 1 < r0 + 8) ? sc[j][3] : 0.f;
            uint32_t h01, l01, h23, l23;
            split2(x0, x1, h01, l01);
            split2(x2, x3, h23, l23);
            PAh[jj >> 1][(jj & 1) * 2 + 0] = h01;
            PAh[jj >> 1][(jj & 1) * 2 + 1] = h23;
            PAl[jj >> 1][(jj & 1) * 2 + 0] = l01;
            PAl[jj >> 1][(jj & 1) * 2 + 1] = l23;
        }
    }

    // ---- Phase 2: out = Q @ Spref_half (K = 64, j = 8 d-tiles) ----
    float o[8][4];
#pragma unroll
    for (int j = 0; j < 8; j++)
#pragma unroll
        for (int q = 0; q < 4; q++) o[j][q] = 0.f;

#pragma unroll
    for (int kk = 0; kk < 4; kk++) {
        uint32_t ah[4], al[4];
        ldmx4(ah, aQA + kk * 32);
        ldmx4(al, aQA + QOFF + kk * 32);
#pragma unroll
        for (int j = 0; j < 8; j++) {
            uint32_t br[4];
            ldmx4(br, aSB + j * (8 * S64 * 2) + kk * 32);
            mma(o[j], ah, br);
            mma(o[j], ah, br + 2);
            mma(o[j], al, br);
        }
    }

    // ---- Phase 3: out += scores @ V_half (K = 128, A from registers) ----
#pragma unroll
    for (int kk = 0; kk < 8; kk++) {
#pragma unroll
        for (int j = 0; j < 8; j++) {
            uint32_t br[4];
            ldmx4t(br, aVB + kk * (16 * S64 * 2) + j * 16);
            mma(o[j], PAh[kk], br);
            mma(o[j], PAh[kk], br + 2);
            mma(o[j], PAl[kk], br);
        }
    }

    // ---- store out[t][dh*64 + d-local] ----
    const int tg = b * T_ + k * C_;
#pragma unroll
    for (int j = 0; j < 8; j++) {
        int d0 = dh * 64 + 8 * j + (L & 3) * 2;
        *(float2*)(out + ((size_t)(tg + r0) * NH_ + h) * D_ + d0) =
            make_float2(o[j][0], o[j][1]);
        *(float2*)(out + ((size_t)(tg + r0 + 8) * NH_ + h) * D_ + d0) =
            make_float2(o[j][2], o[j][3]);
    }
}

// ---------------------------------------------------------------------------
extern "C" void kernel_launch(void* const* d_in, const int* in_sizes, int n_in,
                              void* d_out, int out_size) {
    const float* Q     = (const float*)d_in[0];
    const float* V     = (const float*)d_in[1];
    const float* state = (const float*)d_in[2];
    float* out = (float*)d_out;

    cudaFuncSetAttribute(kA, cudaFuncAttributeMaxDynamicSharedMemorySize, (int)KA_SMEM);
    cudaFuncSetAttribute(kC, cudaFuncAttributeMaxDynamicSharedMemorySize, (int)KC_SMEM);

    bool write_state = (out_size >= (OUT_ELEMS + ST_ELEMS));
    float* out_state = write_state ? (out + OUT_ELEMS) : nullptr;

    kA<<<1024, 256, KA_SMEM>>>(Q, V);
    kB<<<ST_ELEMS / 256, 256>>>(state, out_state);
    kC<<<1024, 256, KC_SMEM>>>(Q, V, out);
}

// round 8
// speedup vs baseline: 1.0049x; 1.0049x over previous
#include <cuda_runtime.h>
#include <cuda_bf16.h>
#include <cstdint>

// Problem constants (fixed by the dataset)
#define B_  4
#define T_  2048
#define NH_ 8
#define N_  64
#define D_  128
#define C_  128          // chunk length
#define NC_ 16           // T_/C_
#define OUT_ELEMS (B_*T_*NH_*D_)   // 8,388,608
#define ST_ELEMS  (B_*NH_*N_*D_)   // 262,144

// Scratch:
//  g_dS        : per-chunk delta-state, layout [bh*16+k][d][n] fp32
//  g_sph/g_spl : prefix state (state + sum_{j<k} dS_j), bf16 hi/lo planes, [blk][d][n]
__device__ float         g_dS [(size_t)512*8192];
__device__ __nv_bfloat16 g_sph[(size_t)512*8192];
__device__ __nv_bfloat16 g_spl[(size_t)512*8192];

// ---------------------------------------------------------------------------
// helpers
// ---------------------------------------------------------------------------
__device__ __forceinline__ uint32_t smem_u32(const void* p) {
    uint32_t a;
    asm("{ .reg .u64 t; cvta.to.shared.u64 t, %1; cvt.u32.u64 %0, t; }"
        : "=r"(a) : "l"(p));
    return a;
}
__device__ __forceinline__ void ldmx4(uint32_t* r, uint32_t a) {
    asm volatile("ldmatrix.sync.aligned.m8n8.x4.shared.b16 {%0,%1,%2,%3}, [%4];"
                 : "=r"(r[0]), "=r"(r[1]), "=r"(r[2]), "=r"(r[3]) : "r"(a));
}
__device__ __forceinline__ void ldmx4t(uint32_t* r, uint32_t a) {
    asm volatile("ldmatrix.sync.aligned.m8n8.x4.trans.shared.b16 {%0,%1,%2,%3}, [%4];"
                 : "=r"(r[0]), "=r"(r[1]), "=r"(r[2]), "=r"(r[3]) : "r"(a));
}
// D += A * B, m16n8k16, row.col, bf16 in / fp32 accum
__device__ __forceinline__ void mma(float* d, const uint32_t* a, const uint32_t* b) {
    asm volatile("mma.sync.aligned.m16n8k16.row.col.f32.bf16.bf16.f32 "
                 "{%0,%1,%2,%3}, {%4,%5,%6,%7}, {%8,%9}, {%0,%1,%2,%3};"
                 : "+f"(d[0]), "+f"(d[1]), "+f"(d[2]), "+f"(d[3])
                 : "r"(a[0]), "r"(a[1]), "r"(a[2]), "r"(a[3]),
                   "r"(b[0]), "r"(b[1]));
}
// fp32 pair -> packed bf16x2 hi plane + residual lo plane (a in low half).
// cvt.rn.bf16x2.f32 packs {b,a}; residuals via exact bit-mask widening.
__device__ __forceinline__ void split2(float a, float b, uint32_t& hi, uint32_t& lo) {
    uint32_t h;
    asm("cvt.rn.bf16x2.f32 %0, %1, %2;" : "=r"(h) : "f"(b), "f"(a));
    float la = a - __uint_as_float(h << 16);
    float lb = b - __uint_as_float(h & 0xffff0000u);
    uint32_t l;
    asm("cvt.rn.bf16x2.f32 %0, %1, %2;" : "=r"(l) : "f"(lb), "f"(la));
    hi = h; lo = l;
}

// padded row stride (elements): 4-bank row offset -> conflict-free ldmatrix
#define S64  72     // rows of 64 bf16

// ============================================================================
// Kernel A (d-split): dS^T[dh*64+dl][n] = sum_c V[c][dh*64+dl] * Q[c][n]
//   smem: V natural [c=128][d-half=64] hi/lo ; Q natural [c=128][n=64] hi/lo
//   A = V^T via ldmatrix.trans ; B = Q^T via ldmatrix.trans (plane-mixed x4)
// grid = 1024 (cidx*2+dh), 256 threads, 3 CTAs/SM
// warps: wd = w&3 (16-row d tile), nh = w>>2 (32-col n half); j = 4 n8 tiles
// ============================================================================
#define KA_SMEM ((size_t)(4*128*S64)*2)   // 73,728 B

__global__ __launch_bounds__(256, 3) void kA(const float* __restrict__ Q,
                                             const float* __restrict__ V) {
    extern __shared__ __nv_bfloat16 sm[];
    __nv_bfloat16* Vh = sm;                  // [128][S64]
    __nv_bfloat16* Vl = Vh + 128 * S64;
    __nv_bfloat16* Qh = Vl + 128 * S64;      // [128][S64]
    __nv_bfloat16* Ql = Qh + 128 * S64;

    const int tid = threadIdx.x, w = tid >> 5, L = tid & 31;
    const int cidx = blockIdx.x >> 1, dh = blockIdx.x & 1;
    const int k = cidx & 15, bh = cidx >> 4;
    const int b = bh >> 3, h = bh & 7;

    const float* Qb = Q + ((size_t)(b * T_ + k * C_) * NH_ + h) * N_;
    const float* Vb = V + (size_t)(b * T_ + k * C_) * D_ + dh * 64;

    // Q natural [c][n]: coalesced float4 loads
#pragma unroll
    for (int it = 0; it < 8; it++) {
        int idx = tid + it * 256;                 // 2048 float4
        int n4 = idx & 15, c = idx >> 4;
        float4 q = *(const float4*)(Qb + (size_t)c * (NH_ * N_) + n4 * 4);
        uint32_t h0, l0, h1, l1;
        split2(q.x, q.y, h0, l0);
        split2(q.z, q.w, h1, l1);
        *(uint2*)(Qh + c * S64 + n4 * 4) = make_uint2(h0, h1);
        *(uint2*)(Ql + c * S64 + n4 * 4) = make_uint2(l0, l1);
    }
    // V natural [c][d-half]
#pragma unroll
    for (int it = 0; it < 8; it++) {
        int idx = tid + it * 256;                 // 2048 float4
        int d4 = idx & 15, c = idx >> 4;
        float4 v = *(const float4*)(Vb + (size_t)c * D_ + d4 * 4);
        uint32_t h0, l0, h1, l1;
        split2(v.x, v.y, h0, l0);
        split2(v.z, v.w, h1, l1);
        *(uint2*)(Vh + c * S64 + d4 * 4) = make_uint2(h0, h1);
        *(uint2*)(Vl + c * S64 + d4 * 4) = make_uint2(l0, l1);
    }
    __syncthreads();

    const int wd = w & 3, nh = w >> 2;
    // A (V^T, m = d-local rows 16wd..16wd+15) trans x4
    const uint32_t aA = smem_u32(
        Vh + ((L & 7) + ((L >> 4) << 3)) * S64 + 16 * wd + (((L >> 3) & 1) << 3));
    const uint32_t VPL = 128 * S64 * 2;          // hi->lo plane (bytes)
    // B (Q^T) trans x4 plane-mixed: lanes 0-15 hi rows c0-15, lanes 16-31 lo
    const uint32_t aB = smem_u32((L < 16 ? Qh : Ql) + (L & 15) * S64) + nh * 64;

    float acc[4][4];
#pragma unroll
    for (int j = 0; j < 4; j++)
#pragma unroll
        for (int q = 0; q < 4; q++) acc[j][q] = 0.f;

#pragma unroll
    for (int kk = 0; kk < 8; kk++) {
        uint32_t ah[4], al[4];
        ldmx4t(ah, aA + kk * (16 * S64 * 2));
        ldmx4t(al, aA + VPL + kk * (16 * S64 * 2));
#pragma unroll
        for (int j = 0; j < 4; j++) {
            uint32_t br[4];   // {bh0, bh1, bl0, bl1}
            ldmx4t(br, aB + kk * (16 * S64 * 2) + j * 16);
            mma(acc[j], ah, br);
            mma(acc[j], ah, br + 2);
            mma(acc[j], al, br);
        }
    }

    const int r0 = dh * 64 + 16 * wd + (L >> 2);
    const int cc = nh * 32 + (L & 3) * 2;
    float* op = g_dS + (size_t)cidx * 8192;
#pragma unroll
    for (int j = 0; j < 4; j++) {
        *(float2*)(op + (size_t)r0 * 64 + 8 * j + cc)       = make_float2(acc[j][0], acc[j][1]);
        *(float2*)(op + (size_t)(r0 + 8) * 64 + 8 * j + cc) = make_float2(acc[j][2], acc[j][3]);
    }
}

// ============================================================================
// Kernel B: exclusive prefix over the 16 chunks -> bf16 hi/lo planes + new_state
// ============================================================================
__global__ void kB(const float* __restrict__ state, float* __restrict__ out_state) {
    int gid = blockIdx.x * 256 + threadIdx.x;       // < 262144
    int bh = gid >> 13, dn = gid & 8191;
    int d = dn >> 6, n = dn & 63;
    const size_t base = (size_t)bh * NC_ * 8192 + dn;
    float run = state[((size_t)bh * 64 + n) * 128 + d];
#pragma unroll
    for (int k = 0; k < NC_; k++) {
        float v = g_dS[base + (size_t)k * 8192];
        uint32_t hi, lo;
        split2(run, 0.f, hi, lo);
        g_sph[base + (size_t)k * 8192] = __ushort_as_bfloat16((unsigned short)(hi & 0xffff));
        g_spl[base + (size_t)k * 8192] = __ushort_as_bfloat16((unsigned short)(lo & 0xffff));
        run += v;
    }
    if (out_state) out_state[((size_t)bh * 64 + n) * 128 + d] = run;
}

// ============================================================================
// Kernel C (d-split): per (chunk, d-half):
//   scores = tril(Q Q^T, -1)   (full u range, register accum, masked -> A frags)
//   out[:, dh] = Q @ Spref[:, dh] + scores @ V[:, dh]
//   smem: Q natural [t][n] hi/lo ; Spref^T [d-local 64][n] hi/lo ;
//         V natural [u][d-local 64] hi/lo
// grid = 1024 (cidx*2+dh), 256 threads, 2 CTAs/SM
// ============================================================================
#define KC_SMEM ((size_t)(2*128*S64 + 2*64*S64 + 2*128*S64)*2)   // 92,160 B

__global__ __launch_bounds__(256, 2) void kC(const float* __restrict__ Q,
                                             const float* __restrict__ V,
                                             float* __restrict__ out) {
    extern __shared__ __nv_bfloat16 sm[];
    __nv_bfloat16* Qh = sm;                 // [128][S64]  Q[t][n]
    __nv_bfloat16* Ql = Qh + 128 * S64;
    __nv_bfloat16* Sh = Ql + 128 * S64;     // [64][S64]   Spref^T[d-local][n]
    __nv_bfloat16* Sl = Sh + 64 * S64;
    __nv_bfloat16* Vh = Sl + 64 * S64;      // [128][S64]  V[u][d-local]
    __nv_bfloat16* Vl = Vh + 128 * S64;

    const int tid = threadIdx.x, w = tid >> 5, L = tid & 31;
    const int cidx = blockIdx.x >> 1, dh = blockIdx.x & 1;
    const int k = cidx & 15, bh = cidx >> 4;
    const int b = bh >> 3, h = bh & 7;

    const float* Qb = Q + ((size_t)(b * T_ + k * C_) * NH_ + h) * N_;
    const float* Vb = V + (size_t)(b * T_ + k * C_) * D_ + dh * 64;

    // Q natural [t][n]
#pragma unroll
    for (int it = 0; it < 8; it++) {
        int idx = tid + it * 256;                 // 2048 float4
        int n4 = idx & 15, t = idx >> 4;
        float4 q = *(const float4*)(Qb + (size_t)t * (NH_ * N_) + n4 * 4);
        uint32_t h0, l0, h1, l1;
        split2(q.x, q.y, h0, l0);
        split2(q.z, q.w, h1, l1);
        *(uint2*)(Qh + t * S64 + n4 * 4) = make_uint2(h0, h1);
        *(uint2*)(Ql + t * S64 + n4 * 4) = make_uint2(l0, l1);
    }
    // Spref planes: straight 16B copies of [d][n] bf16 (rows dh*64 .. dh*64+63)
#pragma unroll
    for (int it = 0; it < 2; it++) {
        int idx = tid + it * 256;                 // 512 uint4 per plane
        int ch = idx & 7, dl = idx >> 3;
        size_t sbase = (size_t)cidx * 8192 + (size_t)(dh * 64 + dl) * 64 + ch * 8;
        *(uint4*)(Sh + dl * S64 + ch * 8) = *(const uint4*)(g_sph + sbase);
        *(uint4*)(Sl + dl * S64 + ch * 8) = *(const uint4*)(g_spl + sbase);
    }
    // V natural [u][d-local]
#pragma unroll
    for (int it = 0; it < 8; it++) {
        int idx = tid + it * 256;                 // 2048 float4
        int d4 = idx & 15, u = idx >> 4;
        float4 v = *(const float4*)(Vb + (size_t)u * D_ + d4 * 4);
        uint32_t h0, l0, h1, l1;
        split2(v.x, v.y, h0, l0);
        split2(v.z, v.w, h1, l1);
        *(uint2*)(Vh + u * S64 + d4 * 4) = make_uint2(h0, h1);
        *(uint2*)(Vl + u * S64 + d4 * 4) = make_uint2(l0, l1);
    }
    __syncthreads();

    const int Lm = L & 15;
    // A (Q rows 16w..16w+15) non-trans x4 (per plane)
    const uint32_t aQA = smem_u32(Qh + (16 * w + Lm) * S64 + ((L >> 4) << 3));
    const uint32_t QOFF = 128 * S64 * 2;     // hi -> lo plane (bytes)
    // B non-trans plane-mixed x4 (rows j*8+(L&7), col-half (L>>3)&1)
    const uint32_t aQB = smem_u32((L < 16 ? Qh : Ql) + (L & 7) * S64 + (((L >> 3) & 1) << 3));
    const uint32_t aSB = smem_u32((L < 16 ? Sh : Sl) + (L & 7) * S64 + (((L >> 3) & 1) << 3));
    // B (V^T) trans plane-mixed x4: lanes 0-15 hi rows u0-15, lanes 16-31 lo
    const uint32_t aVB = smem_u32((L < 16 ? Vh : Vl) + (L & 15) * S64);

    const int r0 = 16 * w + (L >> 2);

    // ---- Phase 1: scores = tril(Q Q^T, -1), two j-halves to cap registers ----
    uint32_t PAh[8][4], PAl[8][4];
#pragma unroll
    for (int jb = 0; jb < 2; jb++) {
        float sc[8][4];
#pragma unroll
        for (int j = 0; j < 8; j++)
#pragma unroll
            for (int q = 0; q < 4; q++) sc[j][q] = 0.f;

#pragma unroll
        for (int kk = 0; kk < 4; kk++) {
            uint32_t ah[4], al[4];
            ldmx4(ah, aQA + kk * 32);
            ldmx4(al, aQA + QOFF + kk * 32);
#pragma unroll
            for (int j = 0; j < 8; j++) {
                uint32_t br[4];
                ldmx4(br, aQB + (jb * 8 + j) * (8 * S64 * 2) + kk * 32);
                mma(sc[j], ah, br);
                mma(sc[j], ah, br + 2);
                mma(sc[j], al, br);
            }
        }
        // mask (strict tril) + convert to phase-3 A-fragments
#pragma unroll
        for (int j = 0; j < 8; j++) {
            int jj = jb * 8 + j;
            int u0 = 8 * jj + (L & 3) * 2;
            float x0 = (u0     < r0)     ? sc[j][0] : 0.f;
            float x1 = (u0 + 1 < r0)     ? sc[j][1] : 0.f;
            float x2 = (u0     < r0 + 8) ? sc[j][2] : 0.f;
            float x3 = (u0 + 1 < r0 + 8) ? sc[j][3] : 0.f;
            uint32_t h01, l01, h23, l23;
            split2(x0, x1, h01, l01);
            split2(x2, x3, h23, l23);
            PAh[jj >> 1][(jj & 1) * 2 + 0] = h01;
            PAh[jj >> 1][(jj & 1) * 2 + 1] = h23;
            PAl[jj >> 1][(jj & 1) * 2 + 0] = l01;
            PAl[jj >> 1][(jj & 1) * 2 + 1] = l23;
        }
    }

    // ---- Phase 2: out = Q @ Spref_half (K = 64, j = 8 d-tiles) ----
    float o[8][4];
#pragma unroll
    for (int j = 0; j < 8; j++)
#pragma unroll
        for (int q = 0; q < 4; q++) o[j][q] = 0.f;

#pragma unroll
    for (int kk = 0; kk < 4; kk++) {
        uint32_t ah[4], al[4];
        ldmx4(ah, aQA + kk * 32);
        ldmx4(al, aQA + QOFF + kk * 32);
#pragma unroll
        for (int j = 0; j < 8; j++) {
            uint32_t br[4];
            ldmx4(br, aSB + j * (8 * S64 * 2) + kk * 32);
            mma(o[j], ah, br);
            mma(o[j], ah, br + 2);
            mma(o[j], al, br);
        }
    }

    // ---- Phase 3: out += scores @ V_half (K = 128, A from registers) ----
#pragma unroll
    for (int kk = 0; kk < 8; kk++) {
#pragma unroll
        for (int j = 0; j < 8; j++) {
            uint32_t br[4];
            ldmx4t(br, aVB + kk * (16 * S64 * 2) + j * 16);
            mma(o[j], PAh[kk], br);
            mma(o[j], PAh[kk], br + 2);
            mma(o[j], PAl[kk], br);
        }
    }

    // ---- store out[t][dh*64 + d-local] ----
    const int tg = b * T_ + k * C_;
#pragma unroll
    for (int j = 0; j < 8; j++) {
        int d0 = dh * 64 + 8 * j + (L & 3) * 2;
        *(float2*)(out + ((size_t)(tg + r0) * NH_ + h) * D_ + d0) =
            make_float2(o[j][0], o[j][1]);
        *(float2*)(out + ((size_t)(tg + r0 + 8) * NH_ + h) * D_ + d0) =
            make_float2(o[j][2], o[j][3]);
    }
}

// ---------------------------------------------------------------------------
extern "C" void kernel_launch(void* const* d_in, const int* in_sizes, int n_in,
                              void* d_out, int out_size) {
    const float* Q     = (const float*)d_in[0];
    const float* V     = (const float*)d_in[1];
    const float* state = (const float*)d_in[2];
    float* out = (float*)d_out;

    cudaFuncSetAttribute(kA, cudaFuncAttributeMaxDynamicSharedMemorySize, (int)KA_SMEM);
    cudaFuncSetAttribute(kC, cudaFuncAttributeMaxDynamicSharedMemorySize, (int)KC_SMEM);

    bool write_state = (out_size >= (OUT_ELEMS + ST_ELEMS));
    float* out_state = write_state ? (out + OUT_ELEMS) : nullptr;

    kA<<<1024, 256, KA_SMEM>>>(Q, V);
    kB<<<ST_ELEMS / 256, 256>>>(state, out_state);
    kC<<<1024, 256, KC_SMEM>>>(Q, V, out);
}